// round 6
// baseline (speedup 1.0000x reference)
#include <cuda_runtime.h>
#include <cuda_bf16.h>

#define N_NODES 100000
#define N_EDGES 1600000
#define D_IN    128
#define D_OUT   64

// Scratch for h = x @ W  (25.6 MB; __device__ global per allocation rules)
__device__ float g_h[(size_t)N_NODES * D_OUT];

// ---------------------------------------------------------------------------
// Kernel 1: zero the output (d_out is poisoned to 0xAA)
// ---------------------------------------------------------------------------
__global__ void zero_out_kernel(float4* __restrict__ out, int n4) {
    int i = blockIdx.x * blockDim.x + threadIdx.x;
    if (i < n4) out[i] = make_float4(0.f, 0.f, 0.f, 0.f);
}

// ---------------------------------------------------------------------------
// Kernel 2: h = x @ W
// Block: 256 threads = (4 col-groups) x (64 row-groups). Each thread computes
// a 4-row x 16-col register tile. W lives in smem (32 KB), broadcast reads.
// ---------------------------------------------------------------------------
__global__ __launch_bounds__(256, 2)
void gemm_kernel(const float* __restrict__ x, const float* __restrict__ W) {
    __shared__ float4 sW[D_IN][D_OUT / 4];   // [128][16] float4 = 32 KB

    int tid = threadIdx.x;
    // cooperative load of W (2048 float4)
    const float4* W4 = (const float4*)W;
    #pragma unroll
    for (int i = tid; i < D_IN * D_OUT / 4; i += 256)
        ((float4*)sW)[i] = W4[i];
    __syncthreads();

    int tx = tid & 3;          // col group: cols [tx*16, tx*16+16)
    int ty = tid >> 2;         // row group: 4 rows each
    int m0 = blockIdx.x * 256 + ty * 4;
    int j0 = tx * 4;           // float4 column index base (16 floats)

    float4 acc[4][4];
    #pragma unroll
    for (int r = 0; r < 4; r++)
        #pragma unroll
        for (int q = 0; q < 4; q++)
            acc[r][q] = make_float4(0.f, 0.f, 0.f, 0.f);

    const float4* x4 = (const float4*)x;

    for (int k4 = 0; k4 < D_IN / 4; k4++) {
        float xs[4][4];
        #pragma unroll
        for (int r = 0; r < 4; r++) {
            int m = m0 + r;
            float4 v = (m < N_NODES) ? x4[(size_t)m * (D_IN / 4) + k4]
                                     : make_float4(0.f, 0.f, 0.f, 0.f);
            xs[r][0] = v.x; xs[r][1] = v.y; xs[r][2] = v.z; xs[r][3] = v.w;
        }
        #pragma unroll
        for (int kk = 0; kk < 4; kk++) {
            int k = k4 * 4 + kk;
            float4 w0 = sW[k][j0 + 0];
            float4 w1 = sW[k][j0 + 1];
            float4 w2 = sW[k][j0 + 2];
            float4 w3 = sW[k][j0 + 3];
            #pragma unroll
            for (int r = 0; r < 4; r++) {
                float a = xs[r][kk];
                acc[r][0].x += a * w0.x; acc[r][0].y += a * w0.y;
                acc[r][0].z += a * w0.z; acc[r][0].w += a * w0.w;
                acc[r][1].x += a * w1.x; acc[r][1].y += a * w1.y;
                acc[r][1].z += a * w1.z; acc[r][1].w += a * w1.w;
                acc[r][2].x += a * w2.x; acc[r][2].y += a * w2.y;
                acc[r][2].z += a * w2.z; acc[r][2].w += a * w2.w;
                acc[r][3].x += a * w3.x; acc[r][3].y += a * w3.y;
                acc[r][3].z += a * w3.z; acc[r][3].w += a * w3.w;
            }
        }
    }

    #pragma unroll
    for (int r = 0; r < 4; r++) {
        int m = m0 + r;
        if (m < N_NODES) {
            float4* hp = (float4*)(g_h + (size_t)m * D_OUT) + j0;
            hp[0] = acc[r][0];
            hp[1] = acc[r][1];
            hp[2] = acc[r][2];
            hp[3] = acc[r][3];
        }
    }
}

// ---------------------------------------------------------------------------
// Kernel 3: scatter-add. 16 threads per edge, each handles 4 floats via
// vectorized L2 reduction (red.global.add.v4.f32, sm_90+).
// h fits in L2 (25.6 MB) so gathers are L2 hits.
// ---------------------------------------------------------------------------
__global__ __launch_bounds__(256)
void scatter_kernel(const int* __restrict__ edge_index, float* __restrict__ out) {
    int gid = blockIdx.x * blockDim.x + threadIdx.x;
    int e = gid >> 4;
    if (e >= N_EDGES) return;
    int c = (gid & 15) << 2;   // column offset 0,4,...,60

    int src = __ldg(edge_index + e);
    int dst = __ldg(edge_index + N_EDGES + e);

    float4 v = *(const float4*)(g_h + (size_t)src * D_OUT + c);
    float* p = out + (size_t)dst * D_OUT + c;
    asm volatile("red.global.add.v4.f32 [%0], {%1,%2,%3,%4};"
                 :: "l"(p), "f"(v.x), "f"(v.y), "f"(v.z), "f"(v.w)
                 : "memory");
}

// ---------------------------------------------------------------------------
// Kernel 4: out = relu(out + b)
// ---------------------------------------------------------------------------
__global__ void finish_kernel(float4* __restrict__ out,
                              const float* __restrict__ b, int n4) {
    int i = blockIdx.x * blockDim.x + threadIdx.x;
    if (i >= n4) return;
    int c = (i & (D_OUT / 4 - 1)) << 2;   // column base within row
    float4 v = out[i];
    v.x = fmaxf(v.x + __ldg(b + c + 0), 0.f);
    v.y = fmaxf(v.y + __ldg(b + c + 1), 0.f);
    v.z = fmaxf(v.z + __ldg(b + c + 2), 0.f);
    v.w = fmaxf(v.w + __ldg(b + c + 3), 0.f);
    out[i] = v;
}

// ---------------------------------------------------------------------------
extern "C" void kernel_launch(void* const* d_in, const int* in_sizes, int n_in,
                              void* d_out, int out_size) {
    const float* x          = (const float*)d_in[0];   // [100000, 128]
    const int*   edge_index = (const int*)d_in[1];     // [2, 1600000]
    const float* W          = (const float*)d_in[2];   // [128, 64]
    const float* b          = (const float*)d_in[3];   // [64]
    float*       out        = (float*)d_out;           // [100000, 64]

    int n4 = (N_NODES * D_OUT) / 4;   // 1.6M float4

    // 1) zero output
    zero_out_kernel<<<(n4 + 255) / 256, 256>>>((float4*)out, n4);

    // 2) h = x @ W
    gemm_kernel<<<(N_NODES + 255) / 256, 256>>>(x, W);

    // 3) scatter-add over edges (16 threads/edge)
    long long sthreads = (long long)N_EDGES * 16;
    scatter_kernel<<<(int)((sthreads + 255) / 256), 256>>>(edge_index, out);

    // 4) bias + relu
    finish_kernel<<<(n4 + 255) / 256, 256>>>((float4*)out, b, n4);
}

// round 7
// speedup vs baseline: 1.0141x; 1.0141x over previous
#include <cuda_runtime.h>
#include <cuda_bf16.h>

#define N_NODES 100000
#define N_EDGES 1600000
#define D_IN    128
#define D_OUT   64

typedef unsigned long long u64;

// Scratch for h = x @ W  (25.6 MB; __device__ global per allocation rules)
__device__ float g_h[(size_t)N_NODES * D_OUT];

// ---------------------------------------------------------------------------
// packed f32x2 helpers (Blackwell FFMA2 path — only reachable via PTX)
// ---------------------------------------------------------------------------
__device__ __forceinline__ void ffma2(u64& d, u64 a, u64 b, u64 c) {
    asm("fma.rn.f32x2 %0, %1, %2, %3;" : "=l"(d) : "l"(a), "l"(b), "l"(c));
}
__device__ __forceinline__ u64 pack2(float lo, float hi) {
    u64 r;
    asm("mov.b64 %0, {%1, %2};" : "=l"(r) : "f"(lo), "f"(hi));
    return r;
}

// ---------------------------------------------------------------------------
// Kernel 1: zero the output (d_out is poisoned to 0xAA)
// ---------------------------------------------------------------------------
__global__ void zero_out_kernel(float4* __restrict__ out, int n4) {
    int i = blockIdx.x * blockDim.x + threadIdx.x;
    if (i < n4) out[i] = make_float4(0.f, 0.f, 0.f, 0.f);
}

// ---------------------------------------------------------------------------
// Kernel 2: h = x @ W  using packed f32x2 FMA (2 cols per register).
// Block: 256 threads = (4 col-groups) x (64 row-groups). Each thread computes
// a 4-row x 16-col tile as 4x8 packed f32x2 accumulators.
// W lives in smem as packed column pairs (32 KB), broadcast reads.
// ---------------------------------------------------------------------------
__global__ __launch_bounds__(256, 2)
void gemm_kernel(const float* __restrict__ x, const float* __restrict__ W) {
    __shared__ u64 sW[D_IN][D_OUT / 2];   // [128][32] u64 = 32 KB

    int tid = threadIdx.x;
    // cooperative load of W (2048 float4 -> packed pairs)
    const float4* W4 = (const float4*)W;
    #pragma unroll
    for (int i = tid; i < D_IN * D_OUT / 4; i += 256) {
        float4 v = W4[i];
        int k = i >> 4;          // row of W
        int j = i & 15;          // float4 index within row
        sW[k][2 * j + 0] = pack2(v.x, v.y);
        sW[k][2 * j + 1] = pack2(v.z, v.w);
    }
    __syncthreads();

    int tx = tid & 3;            // col group: cols [tx*16, tx*16+16)
    int ty = tid >> 2;           // row group: 4 rows each
    int m0 = blockIdx.x * 256 + ty * 4;
    int j0 = tx * 8;             // u64 column index base (8 packed pairs = 16 floats)

    u64 acc[4][8];
    #pragma unroll
    for (int r = 0; r < 4; r++)
        #pragma unroll
        for (int q = 0; q < 8; q++)
            acc[r][q] = 0ull;    // bit pattern of (0.0f, 0.0f)

    const float4* x4 = (const float4*)x;

    for (int k4 = 0; k4 < D_IN / 4; k4++) {
        float xs[4][4];
        #pragma unroll
        for (int r = 0; r < 4; r++) {
            int m = m0 + r;
            float4 v = (m < N_NODES) ? x4[(size_t)m * (D_IN / 4) + k4]
                                     : make_float4(0.f, 0.f, 0.f, 0.f);
            xs[r][0] = v.x; xs[r][1] = v.y; xs[r][2] = v.z; xs[r][3] = v.w;
        }
        #pragma unroll
        for (int kk = 0; kk < 4; kk++) {
            int k = k4 * 4 + kk;
            u64 w[8];
            #pragma unroll
            for (int q = 0; q < 8; q++)
                w[q] = sW[k][j0 + q];
            #pragma unroll
            for (int r = 0; r < 4; r++) {
                u64 a2 = pack2(xs[r][kk], xs[r][kk]);
                #pragma unroll
                for (int q = 0; q < 8; q++)
                    ffma2(acc[r][q], a2, w[q], acc[r][q]);
            }
        }
    }

    #pragma unroll
    for (int r = 0; r < 4; r++) {
        int m = m0 + r;
        if (m < N_NODES) {
            ulonglong2* hp = (ulonglong2*)(g_h + (size_t)m * D_OUT) + tx * 4;
            #pragma unroll
            for (int q = 0; q < 4; q++) {
                ulonglong2 s; s.x = acc[r][2 * q]; s.y = acc[r][2 * q + 1];
                hp[q] = s;
            }
        }
    }
}

// ---------------------------------------------------------------------------
// Kernel 3: scatter-add. 16 threads per edge, each handles 4 floats via
// vectorized L2 reduction (red.global.add.v4.f32, sm_90+).
// h fits in L2 (25.6 MB) so gathers are L2 hits.
// ---------------------------------------------------------------------------
__global__ __launch_bounds__(256)
void scatter_kernel(const int* __restrict__ edge_index, float* __restrict__ out) {
    int gid = blockIdx.x * blockDim.x + threadIdx.x;
    int e = gid >> 4;
    if (e >= N_EDGES) return;
    int c = (gid & 15) << 2;   // column offset 0,4,...,60

    int src = __ldg(edge_index + e);
    int dst = __ldg(edge_index + N_EDGES + e);

    float4 v = *(const float4*)(g_h + (size_t)src * D_OUT + c);
    float* p = out + (size_t)dst * D_OUT + c;
    asm volatile("red.global.add.v4.f32 [%0], {%1,%2,%3,%4};"
                 :: "l"(p), "f"(v.x), "f"(v.y), "f"(v.z), "f"(v.w)
                 : "memory");
}

// ---------------------------------------------------------------------------
// Kernel 4: out = relu(out + b)
// ---------------------------------------------------------------------------
__global__ void finish_kernel(float4* __restrict__ out,
                              const float* __restrict__ b, int n4) {
    int i = blockIdx.x * blockDim.x + threadIdx.x;
    if (i >= n4) return;
    int c = (i & (D_OUT / 4 - 1)) << 2;   // column base within row
    float4 v = out[i];
    v.x = fmaxf(v.x + __ldg(b + c + 0), 0.f);
    v.y = fmaxf(v.y + __ldg(b + c + 1), 0.f);
    v.z = fmaxf(v.z + __ldg(b + c + 2), 0.f);
    v.w = fmaxf(v.w + __ldg(b + c + 3), 0.f);
    out[i] = v;
}

// ---------------------------------------------------------------------------
extern "C" void kernel_launch(void* const* d_in, const int* in_sizes, int n_in,
                              void* d_out, int out_size) {
    const float* x          = (const float*)d_in[0];   // [100000, 128]
    const int*   edge_index = (const int*)d_in[1];     // [2, 1600000]
    const float* W          = (const float*)d_in[2];   // [128, 64]
    const float* b          = (const float*)d_in[3];   // [64]
    float*       out        = (float*)d_out;           // [100000, 64]

    int n4 = (N_NODES * D_OUT) / 4;   // 1.6M float4

    // 1) zero output
    zero_out_kernel<<<(n4 + 255) / 256, 256>>>((float4*)out, n4);

    // 2) h = x @ W  (packed f32x2 FMA)
    gemm_kernel<<<(N_NODES + 255) / 256, 256>>>(x, W);

    // 3) scatter-add over edges (16 threads/edge)
    long long sthreads = (long long)N_EDGES * 16;
    scatter_kernel<<<(int)((sthreads + 255) / 256), 256>>>(edge_index, out);

    // 4) bias + relu
    finish_kernel<<<(n4 + 255) / 256, 256>>>((float4*)out, b, n4);
}

// round 8
// speedup vs baseline: 1.0796x; 1.0646x over previous
#include <cuda_runtime.h>
#include <cuda_bf16.h>

#define N_NODES 100000
#define N_EDGES 1600000
#define D_IN    128
#define D_OUT   64
#define SCAN_BLK 1024
#define NBLK ((N_NODES + SCAN_BLK - 1) / SCAN_BLK)   // 98

typedef unsigned long long u64;

// __device__ scratch (no allocs allowed)
__device__ float g_h[(size_t)N_NODES * D_OUT];        // 25.6 MB
__device__ int   g_count[N_NODES];
__device__ int   g_offset[N_NODES];
__device__ int   g_cursor[N_NODES];
__device__ int   g_src_sorted[N_EDGES];               // 6.4 MB
__device__ int   g_blocksums[NBLK];

// ---------------------------------------------------------------------------
// packed f32x2 helpers (Blackwell FFMA2 path — only reachable via PTX)
// ---------------------------------------------------------------------------
__device__ __forceinline__ void ffma2(u64& d, u64 a, u64 b, u64 c) {
    asm("fma.rn.f32x2 %0, %1, %2, %3;" : "=l"(d) : "l"(a), "l"(b), "l"(c));
}
__device__ __forceinline__ u64 pack2(float lo, float hi) {
    u64 r;
    asm("mov.b64 %0, {%1, %2};" : "=l"(r) : "f"(lo), "f"(hi));
    return r;
}

// ---------------------------------------------------------------------------
// Sort chain kernel 0: zero the histogram
// ---------------------------------------------------------------------------
__global__ void zero_count_kernel() {
    int i = blockIdx.x * blockDim.x + threadIdx.x;
    if (i < N_NODES) g_count[i] = 0;
}

// Sort chain kernel 1: histogram of dst
__global__ void hist_kernel(const int* __restrict__ edge_index) {
    int e = blockIdx.x * blockDim.x + threadIdx.x;
    if (e < N_EDGES) atomicAdd(&g_count[__ldg(edge_index + N_EDGES + e)], 1);
}

// Sort chain kernel 2a: per-block sums of counts
__global__ __launch_bounds__(SCAN_BLK)
void scanA_kernel() {
    __shared__ int s[SCAN_BLK];
    int tid = threadIdx.x;
    int i = blockIdx.x * SCAN_BLK + tid;
    s[tid] = (i < N_NODES) ? g_count[i] : 0;
    __syncthreads();
    #pragma unroll
    for (int st = SCAN_BLK / 2; st > 0; st >>= 1) {
        if (tid < st) s[tid] += s[tid + st];
        __syncthreads();
    }
    if (tid == 0) g_blocksums[blockIdx.x] = s[0];
}

// Sort chain kernel 2b: exclusive scan of block sums (single block)
__global__ void scanB_kernel() {
    __shared__ int s[NBLK];
    int tid = threadIdx.x;
    if (tid < NBLK) s[tid] = g_blocksums[tid];
    __syncthreads();
    if (tid == 0) {
        int acc = 0;
        #pragma unroll 1
        for (int i = 0; i < NBLK; i++) { int t = s[i]; s[i] = acc; acc += t; }
    }
    __syncthreads();
    if (tid < NBLK) g_blocksums[tid] = s[tid];
}

// Sort chain kernel 2c: per-block exclusive scan + block offset -> offsets & cursors
__global__ __launch_bounds__(SCAN_BLK)
void scanC_kernel() {
    __shared__ int buf[2][SCAN_BLK];
    int tid = threadIdx.x;
    int i = blockIdx.x * SCAN_BLK + tid;
    int v = (i < N_NODES) ? g_count[i] : 0;
    int pin = 0;
    buf[pin][tid] = v;
    __syncthreads();
    #pragma unroll
    for (int st = 1; st < SCAN_BLK; st <<= 1) {
        int pout = pin ^ 1;
        int val = buf[pin][tid];
        if (tid >= st) val += buf[pin][tid - st];
        buf[pout][tid] = val;
        pin = pout;
        __syncthreads();
    }
    if (i < N_NODES) {
        int excl = buf[pin][tid] - v + g_blocksums[blockIdx.x];
        g_offset[i] = excl;
        g_cursor[i] = excl;
    }
}

// Sort chain kernel 3: bucket-scatter src indices into dst-sorted order
__global__ void bucket_scatter_kernel(const int* __restrict__ edge_index) {
    int e = blockIdx.x * blockDim.x + threadIdx.x;
    if (e >= N_EDGES) return;
    int src = __ldg(edge_index + e);
    int dst = __ldg(edge_index + N_EDGES + e);
    int pos = atomicAdd(&g_cursor[dst], 1);
    g_src_sorted[pos] = src;
}

// ---------------------------------------------------------------------------
// GEMM: h = x @ W  using packed f32x2 FMA (unchanged from R6)
// ---------------------------------------------------------------------------
__global__ __launch_bounds__(256, 2)
void gemm_kernel(const float* __restrict__ x, const float* __restrict__ W) {
    __shared__ u64 sW[D_IN][D_OUT / 2];   // 32 KB

    int tid = threadIdx.x;
    const float4* W4 = (const float4*)W;
    #pragma unroll
    for (int i = tid; i < D_IN * D_OUT / 4; i += 256) {
        float4 v = W4[i];
        int k = i >> 4;
        int j = i & 15;
        sW[k][2 * j + 0] = pack2(v.x, v.y);
        sW[k][2 * j + 1] = pack2(v.z, v.w);
    }
    __syncthreads();

    int tx = tid & 3;
    int ty = tid >> 2;
    int m0 = blockIdx.x * 256 + ty * 4;
    int j0 = tx * 8;

    u64 acc[4][8];
    #pragma unroll
    for (int r = 0; r < 4; r++)
        #pragma unroll
        for (int q = 0; q < 8; q++)
            acc[r][q] = 0ull;

    const float4* x4 = (const float4*)x;

    for (int k4 = 0; k4 < D_IN / 4; k4++) {
        float xs[4][4];
        #pragma unroll
        for (int r = 0; r < 4; r++) {
            int m = m0 + r;
            float4 v = (m < N_NODES) ? x4[(size_t)m * (D_IN / 4) + k4]
                                     : make_float4(0.f, 0.f, 0.f, 0.f);
            xs[r][0] = v.x; xs[r][1] = v.y; xs[r][2] = v.z; xs[r][3] = v.w;
        }
        #pragma unroll
        for (int kk = 0; kk < 4; kk++) {
            int k = k4 * 4 + kk;
            u64 w[8];
            #pragma unroll
            for (int q = 0; q < 8; q++)
                w[q] = sW[k][j0 + q];
            #pragma unroll
            for (int r = 0; r < 4; r++) {
                u64 a2 = pack2(xs[r][kk], xs[r][kk]);
                #pragma unroll
                for (int q = 0; q < 8; q++)
                    ffma2(acc[r][q], a2, w[q], acc[r][q]);
            }
        }
    }

    #pragma unroll
    for (int r = 0; r < 4; r++) {
        int m = m0 + r;
        if (m < N_NODES) {
            ulonglong2* hp = (ulonglong2*)(g_h + (size_t)m * D_OUT) + tx * 4;
            #pragma unroll
            for (int q = 0; q < 4; q++) {
                ulonglong2 s; s.x = acc[r][2 * q]; s.y = acc[r][2 * q + 1];
                hp[q] = s;
            }
        }
    }
}

// ---------------------------------------------------------------------------
// Reduce: one warp per dst node. Gather h[src] rows for its edge bucket,
// accumulate in registers (2 floats/lane), write relu(acc + b) once.
// Replaces zero_out + scatter-atomics + finish.
// ---------------------------------------------------------------------------
__global__ __launch_bounds__(256)
void reduce_kernel(float* __restrict__ out, const float* __restrict__ b) {
    int warp = threadIdx.x >> 5;
    int lane = threadIdx.x & 31;
    int n = blockIdx.x * 8 + warp;
    if (n >= N_NODES) return;

    int start = g_offset[n];
    int cnt   = g_count[n];

    float a0 = 0.f, a1 = 0.f;
    for (int base = 0; base < cnt; base += 32) {
        int my = 0;
        if (base + lane < cnt) my = __ldg(&g_src_sorted[start + base + lane]);
        int m = min(32, cnt - base);
        #pragma unroll 4
        for (int j = 0; j < m; j++) {
            int src = __shfl_sync(0xffffffffu, my, j);
            const float* hp = g_h + (size_t)src * D_OUT;
            a0 += __ldg(hp + lane);
            a1 += __ldg(hp + 32 + lane);
        }
    }
    a0 = fmaxf(a0 + __ldg(b + lane), 0.f);
    a1 = fmaxf(a1 + __ldg(b + 32 + lane), 0.f);
    out[(size_t)n * D_OUT + lane]      = a0;
    out[(size_t)n * D_OUT + 32 + lane] = a1;
}

// ---------------------------------------------------------------------------
extern "C" void kernel_launch(void* const* d_in, const int* in_sizes, int n_in,
                              void* d_out, int out_size) {
    const float* x          = (const float*)d_in[0];   // [100000, 128]
    const int*   edge_index = (const int*)d_in[1];     // [2, 1600000]
    const float* W          = (const float*)d_in[2];   // [128, 64]
    const float* b          = (const float*)d_in[3];   // [64]
    float*       out        = (float*)d_out;           // [100000, 64]

    // counting sort of edges by dst
    zero_count_kernel<<<(N_NODES + 255) / 256, 256>>>();
    hist_kernel<<<(N_EDGES + 255) / 256, 256>>>(edge_index);
    scanA_kernel<<<NBLK, SCAN_BLK>>>();
    scanB_kernel<<<1, 128>>>();
    scanC_kernel<<<NBLK, SCAN_BLK>>>();
    bucket_scatter_kernel<<<(N_EDGES + 255) / 256, 256>>>(edge_index);

    // h = x @ W (packed f32x2 FMA)
    gemm_kernel<<<(N_NODES + 255) / 256, 256>>>(x, W);

    // gather-reduce + bias + relu (one warp per node)
    reduce_kernel<<<(N_NODES + 7) / 8, 256>>>(out, b);
}

// round 9
// speedup vs baseline: 1.1660x; 1.0801x over previous
#include <cuda_runtime.h>
#include <cuda_fp16.h>
#include <cuda_bf16.h>

#define N_NODES 100000
#define N_EDGES 1600000
#define D_IN    128
#define D_OUT   64
#define SCAN_BLK 1024
#define NBLK ((N_NODES + SCAN_BLK - 1) / SCAN_BLK)   // 98

typedef unsigned long long u64;

// __device__ scratch (no allocs allowed)
__device__ __half2 g_h2[(size_t)N_NODES * (D_OUT / 2)];  // 12.8 MB, fp16 h
__device__ int   g_count[N_NODES];
__device__ int   g_offset[N_NODES];
__device__ int   g_cursor[N_NODES];
__device__ int   g_src_sorted[N_EDGES];                  // 6.4 MB
__device__ int   g_blocksums[NBLK];

// ---------------------------------------------------------------------------
// packed f32x2 helpers (Blackwell FFMA2 path — only reachable via PTX)
// ---------------------------------------------------------------------------
__device__ __forceinline__ void ffma2(u64& d, u64 a, u64 b, u64 c) {
    asm("fma.rn.f32x2 %0, %1, %2, %3;" : "=l"(d) : "l"(a), "l"(b), "l"(c));
}
__device__ __forceinline__ u64 pack2(float lo, float hi) {
    u64 r;
    asm("mov.b64 %0, {%1, %2};" : "=l"(r) : "f"(lo), "f"(hi));
    return r;
}
__device__ __forceinline__ void unpack2(u64 v, float& lo, float& hi) {
    asm("mov.b64 {%0, %1}, %2;" : "=f"(lo), "=f"(hi) : "l"(v));
}

// ---------------------------------------------------------------------------
// Sort chain kernel 0: zero the histogram (vectorized)
// ---------------------------------------------------------------------------
__global__ void zero_count_kernel() {
    int i = blockIdx.x * blockDim.x + threadIdx.x;   // int4 index
    if (i < N_NODES / 4)
        ((int4*)g_count)[i] = make_int4(0, 0, 0, 0);
}

// Sort chain kernel 1: histogram of dst (4 edges per thread)
__global__ void hist_kernel(const int* __restrict__ edge_index) {
    int i = blockIdx.x * blockDim.x + threadIdx.x;
    if (i >= N_EDGES / 4) return;
    int4 d = __ldg((const int4*)(edge_index + N_EDGES) + i);
    atomicAdd(&g_count[d.x], 1);
    atomicAdd(&g_count[d.y], 1);
    atomicAdd(&g_count[d.z], 1);
    atomicAdd(&g_count[d.w], 1);
}

// Sort chain kernel 2a: per-block sums of counts
__global__ __launch_bounds__(SCAN_BLK)
void scanA_kernel() {
    __shared__ int s[SCAN_BLK];
    int tid = threadIdx.x;
    int i = blockIdx.x * SCAN_BLK + tid;
    s[tid] = (i < N_NODES) ? g_count[i] : 0;
    __syncthreads();
    #pragma unroll
    for (int st = SCAN_BLK / 2; st > 0; st >>= 1) {
        if (tid < st) s[tid] += s[tid + st];
        __syncthreads();
    }
    if (tid == 0) g_blocksums[blockIdx.x] = s[0];
}

// Sort chain kernel 2b: exclusive scan of block sums (parallel warp scan)
__global__ void scanB_kernel() {
    __shared__ int wsum[4];
    int tid  = threadIdx.x;             // 128 threads
    int lane = tid & 31;
    int w    = tid >> 5;
    int v = (tid < NBLK) ? g_blocksums[tid] : 0;
    int s = v;
    #pragma unroll
    for (int st = 1; st < 32; st <<= 1) {
        int t = __shfl_up_sync(0xffffffffu, s, st);
        if (lane >= st) s += t;
    }
    if (lane == 31) wsum[w] = s;
    __syncthreads();
    if (tid == 0) {
        int acc = 0;
        #pragma unroll
        for (int k = 0; k < 4; k++) { int t = wsum[k]; wsum[k] = acc; acc += t; }
    }
    __syncthreads();
    int excl = s - v + wsum[w];
    if (tid < NBLK) g_blocksums[tid] = excl;
}

// Sort chain kernel 2c: per-block exclusive scan + block offset -> offsets & cursors
__global__ __launch_bounds__(SCAN_BLK)
void scanC_kernel() {
    __shared__ int buf[2][SCAN_BLK];
    int tid = threadIdx.x;
    int i = blockIdx.x * SCAN_BLK + tid;
    int v = (i < N_NODES) ? g_count[i] : 0;
    int pin = 0;
    buf[pin][tid] = v;
    __syncthreads();
    #pragma unroll
    for (int st = 1; st < SCAN_BLK; st <<= 1) {
        int pout = pin ^ 1;
        int val = buf[pin][tid];
        if (tid >= st) val += buf[pin][tid - st];
        buf[pout][tid] = val;
        pin = pout;
        __syncthreads();
    }
    if (i < N_NODES) {
        int excl = buf[pin][tid] - v + g_blocksums[blockIdx.x];
        g_offset[i] = excl;
        g_cursor[i] = excl;
    }
}

// Sort chain kernel 3: bucket-scatter src indices into dst-sorted order
__global__ void bucket_scatter_kernel(const int* __restrict__ edge_index) {
    int e = blockIdx.x * blockDim.x + threadIdx.x;
    if (e >= N_EDGES) return;
    int src = __ldg(edge_index + e);
    int dst = __ldg(edge_index + N_EDGES + e);
    int pos = atomicAdd(&g_cursor[dst], 1);
    g_src_sorted[pos] = src;
}

// ---------------------------------------------------------------------------
// GEMM: h = x @ W, packed f32x2 FMA, fp16 store (f32 accumulate).
// ---------------------------------------------------------------------------
__global__ __launch_bounds__(256, 2)
void gemm_kernel(const float* __restrict__ x, const float* __restrict__ W) {
    __shared__ u64 sW[D_IN][D_OUT / 2];   // 32 KB

    int tid = threadIdx.x;
    const float4* W4 = (const float4*)W;
    #pragma unroll
    for (int i = tid; i < D_IN * D_OUT / 4; i += 256) {
        float4 v = W4[i];
        int k = i >> 4;
        int j = i & 15;
        sW[k][2 * j + 0] = pack2(v.x, v.y);
        sW[k][2 * j + 1] = pack2(v.z, v.w);
    }
    __syncthreads();

    int tx = tid & 3;
    int ty = tid >> 2;
    int m0 = blockIdx.x * 256 + ty * 4;
    int j0 = tx * 8;

    u64 acc[4][8];
    #pragma unroll
    for (int r = 0; r < 4; r++)
        #pragma unroll
        for (int q = 0; q < 8; q++)
            acc[r][q] = 0ull;

    const float4* x4 = (const float4*)x;

    for (int k4 = 0; k4 < D_IN / 4; k4++) {
        float xs[4][4];
        #pragma unroll
        for (int r = 0; r < 4; r++) {
            int m = m0 + r;
            float4 v = (m < N_NODES) ? x4[(size_t)m * (D_IN / 4) + k4]
                                     : make_float4(0.f, 0.f, 0.f, 0.f);
            xs[r][0] = v.x; xs[r][1] = v.y; xs[r][2] = v.z; xs[r][3] = v.w;
        }
        #pragma unroll
        for (int kk = 0; kk < 4; kk++) {
            int k = k4 * 4 + kk;
            u64 w[8];
            #pragma unroll
            for (int q = 0; q < 8; q++)
                w[q] = sW[k][j0 + q];
            #pragma unroll
            for (int r = 0; r < 4; r++) {
                u64 a2 = pack2(xs[r][kk], xs[r][kk]);
                #pragma unroll
                for (int q = 0; q < 8; q++)
                    ffma2(acc[r][q], a2, w[q], acc[r][q]);
            }
        }
    }

    #pragma unroll
    for (int r = 0; r < 4; r++) {
        int m = m0 + r;
        if (m < N_NODES) {
            // 16 cols -> 8 half2 = 32B, two uint4 stores
            uint4 st[2];
            unsigned* sp = (unsigned*)st;
            #pragma unroll
            for (int q = 0; q < 8; q++) {
                float lo, hi;
                unpack2(acc[r][q], lo, hi);
                __half2 hh = __floats2half2_rn(lo, hi);
                sp[q] = *(unsigned*)&hh;
            }
            uint4* hp = (uint4*)(g_h2 + (size_t)m * (D_OUT / 2) + tx * 8);
            hp[0] = st[0];
            hp[1] = st[1];
        }
    }
}

// ---------------------------------------------------------------------------
// Reduce: one warp per dst node. Each edge row is one coalesced 128B request
// (4B half2 per lane). fp32 accumulation, relu(acc+b), single write.
// ---------------------------------------------------------------------------
__global__ __launch_bounds__(256)
void reduce_kernel(float* __restrict__ out, const float* __restrict__ b) {
    int warp = threadIdx.x >> 5;
    int lane = threadIdx.x & 31;
    int n = blockIdx.x * 8 + warp;
    if (n >= N_NODES) return;

    int start = g_offset[n];
    int cnt   = g_count[n];

    float a0 = 0.f, a1 = 0.f;
    for (int base = 0; base < cnt; base += 32) {
        int my = 0;
        if (base + lane < cnt) my = __ldg(&g_src_sorted[start + base + lane]);
        int m = min(32, cnt - base);
        #pragma unroll 8
        for (int j = 0; j < m; j++) {
            int src = __shfl_sync(0xffffffffu, my, j);
            __half2 v = __ldg(g_h2 + (size_t)src * (D_OUT / 2) + lane);
            float2 f = __half22float2(v);
            a0 += f.x;
            a1 += f.y;
        }
    }
    a0 = fmaxf(a0 + __ldg(b + 2 * lane),     0.f);
    a1 = fmaxf(a1 + __ldg(b + 2 * lane + 1), 0.f);
    float2 o; o.x = a0; o.y = a1;
    ((float2*)(out + (size_t)n * D_OUT))[lane] = o;
}

// ---------------------------------------------------------------------------
extern "C" void kernel_launch(void* const* d_in, const int* in_sizes, int n_in,
                              void* d_out, int out_size) {
    const float* x          = (const float*)d_in[0];   // [100000, 128]
    const int*   edge_index = (const int*)d_in[1];     // [2, 1600000]
    const float* W          = (const float*)d_in[2];   // [128, 64]
    const float* b          = (const float*)d_in[3];   // [64]
    float*       out        = (float*)d_out;           // [100000, 64]

    // counting sort of edges by dst
    zero_count_kernel<<<(N_NODES / 4 + 255) / 256, 256>>>();
    hist_kernel<<<(N_EDGES / 4 + 255) / 256, 256>>>(edge_index);
    scanA_kernel<<<NBLK, SCAN_BLK>>>();
    scanB_kernel<<<1, 128>>>();
    scanC_kernel<<<NBLK, SCAN_BLK>>>();
    bucket_scatter_kernel<<<(N_EDGES + 255) / 256, 256>>>(edge_index);

    // h = x @ W (packed f32x2 FMA, fp16 store)
    gemm_kernel<<<(N_NODES + 255) / 256, 256>>>(x, W);

    // gather-reduce + bias + relu (one warp per node)
    reduce_kernel<<<(N_NODES + 7) / 8, 256>>>(out, b);
}